// round 8
// baseline (speedup 1.0000x reference)
#include <cuda_runtime.h>
#include <math.h>
#include <stdint.h>

#define IN_DIM  256
#define OUT_DIM 256   // H*D = 4*64
#define NHEAD   4
#define NMAX    50000
#define EMAX    800000
#define ETOTMAX (EMAX + NMAX)

// ---------------- scratch (__device__ globals; allocation-free) ----------------
__device__ float    g_h[(size_t)NMAX * OUT_DIM];     // 51.2 MB transformed features
__device__ float    g_as[NMAX * NHEAD];
__device__ float    g_ad[NMAX * NHEAD];
__device__ int      g_cnt[NMAX];
__device__ int      g_fill[NMAX];
__device__ int      g_start[NMAX + 1];
__device__ int      g_csr[ETOTMAX];
__device__ float    g_w[(size_t)ETOTMAX * NHEAD];
__device__ float    g_s[NMAX * NHEAD];
// W fragment-packed: pr = (k>>3)*4 + (k&3), element = {hi[k], hi[k+4], lo[k], lo[k+4]} at col n
__device__ uint4    g_wp[(IN_DIM / 2) * OUT_DIM];

__device__ __forceinline__ unsigned tf32_bits(float f) {
    unsigned r; asm("cvt.rna.tf32.f32 %0, %1;" : "=r"(r) : "f"(f)); return r;
}

__device__ __forceinline__ void mma_tf32(float* c, uint32_t a0, uint32_t a1,
                                         uint32_t a2, uint32_t a3,
                                         uint32_t b0, uint32_t b1) {
    asm("mma.sync.aligned.m16n8k8.row.col.f32.tf32.tf32.f32 "
        "{%0,%1,%2,%3},{%4,%5,%6,%7},{%8,%9},{%0,%1,%2,%3};"
        : "+f"(c[0]), "+f"(c[1]), "+f"(c[2]), "+f"(c[3])
        : "r"(a0), "r"(a1), "r"(a2), "r"(a3), "r"(b0), "r"(b1));
}

__device__ __forceinline__ void cp_async16(unsigned* smem_ptr, const void* gptr) {
    uint32_t s = (uint32_t)__cvta_generic_to_shared(smem_ptr);
    asm volatile("cp.async.cg.shared.global [%0], [%1], 16;" :: "r"(s), "l"(gptr) : "memory");
}
#define CP_COMMIT() asm volatile("cp.async.commit_group;" ::: "memory")
#define CP_WAIT0()  asm volatile("cp.async.wait_group 0;" ::: "memory")

__device__ __forceinline__ float lrelu(float x) { return x > 0.f ? x : 0.2f * x; }
__device__ __forceinline__ float4 lrelu4(float4 a) {
    return make_float4(lrelu(a.x), lrelu(a.y), lrelu(a.z), lrelu(a.w));
}
__device__ __forceinline__ float4 add4(float4 a, float4 b) {
    return make_float4(a.x + b.x, a.y + b.y, a.z + b.z, a.w + b.w);
}
__device__ __forceinline__ float4 max4(float4 a, float4 b) {
    return make_float4(fmaxf(a.x, b.x), fmaxf(a.y, b.y), fmaxf(a.z, b.z), fmaxf(a.w, b.w));
}

// ---------------- K0: zero counters + logits accumulators ----------------
__global__ void k_zero(int N) {
    int stride = gridDim.x * blockDim.x;
    int gid = blockIdx.x * blockDim.x + threadIdx.x;
    for (int i = gid; i < 2 * N; i += stride) {
        if (i < N) g_cnt[i] = 0; else g_fill[i - N] = 0;
    }
    for (int i = gid; i < 4 * N; i += stride) { g_as[i] = 0.f; g_ad[i] = 0.f; }
}

// ---------------- K0b: W -> fragment-packed tf32 hi/lo ----------------
__global__ void k_wt(const float* __restrict__ W) {
    int idx = blockIdx.x * blockDim.x + threadIdx.x;     // (pr, n)
    if (idx >= (IN_DIM / 2) * OUT_DIM) return;
    int pr = idx >> 8, n = idx & 255;
    int q = pr >> 2, t = pr & 3;
    int k = q * 8 + t;
    float w0 = W[(size_t)k * OUT_DIM + n];
    float w1 = W[(size_t)(k + 4) * OUT_DIM + n];
    unsigned h0 = tf32_bits(w0), h1 = tf32_bits(w1);
    unsigned l0 = tf32_bits(w0 - __uint_as_float(h0));
    unsigned l1 = tf32_bits(w1 - __uint_as_float(h1));
    g_wp[idx] = make_uint4(h0, h1, l0, l1);
}

// ---------------- K3a: histogram of dst ----------------
__global__ void k_hist(const int* __restrict__ ei, int E, int N) {
    int Etot = E + N;
    int stride = gridDim.x * blockDim.x;
    for (int i = blockIdx.x * blockDim.x + threadIdx.x; i < Etot; i += stride) {
        int dst = (i < E) ? ei[E + i] : (i - E);
        atomicAdd(&g_cnt[dst], 1);
    }
}

// ---------------- K1: GEMM h = x @ W (mma.sync tf32 2-pass) + fused att logits ----------------
// BM=128, BN=128, BK=32; 16 warps, warp tile 32x32; 2 CTAs/SM.
// x tile single-buffered; W fragment-packed uint4, double-buffered via cp.async.
#define XS_STRIDE 36
#define XS_BUF (128 * XS_STRIDE)          // 4608 words
#define WP_ROWSTRIDE 130                  // uint4 units; 130*16 % 128B == 32 -> conflict-free
#define WP_BUF (16 * WP_ROWSTRIDE * 4)    // 8320 words per buffer
#define OFF_XS 0
#define OFF_WP XS_BUF
#define SM_GEMM_WORDS (OFF_WP + 2 * WP_BUF)   // 21248 words
#define SM_GEMM_BYTES (SM_GEMM_WORDS * 4)     // 84992 B
__global__ __launch_bounds__(512, 2) void k_gemm_mma(const float* __restrict__ x,
                                                     const float* __restrict__ att_src,
                                                     const float* __restrict__ att_dst, int N) {
    extern __shared__ unsigned smem[];
    unsigned* xs = smem + OFF_XS;
    int tid = threadIdx.x;
    int wid = tid >> 5, lane = tid & 31;
    int g = lane >> 2, t = lane & 3;
    int m0 = blockIdx.x * 128;
    int n0 = blockIdx.y * 128;
    int wm = (wid & 3) * 32;        // warp row offset
    int wn = (wid >> 2) * 32;       // warp col offset

    float acc[2][4][4];
#pragma unroll
    for (int mt = 0; mt < 2; mt++)
#pragma unroll
        for (int nt = 0; nt < 4; nt++)
#pragma unroll
            for (int i = 0; i < 4; i++) acc[mt][nt][i] = 0.f;

    int xrow = tid >> 2;                 // 0..127
    int xkq  = (tid & 3) * 8;            // 0,8,16,24
    int wprow = tid >> 5;                // 0..15 (packed row this thread copies)
    int wpn   = lane * 4;                // 0..124 (4 consecutive n per thread)
    int grow = m0 + xrow;
    bool xok = grow < N;
    const float* xbase = &x[(size_t)grow * IN_DIM + xkq];

    // prologue: issue W[0] cp.async, prefetch x[0] to regs
    {
        const uint4* wp = &g_wp[(size_t)wprow * OUT_DIM + n0 + wpn];
#pragma unroll
        for (int i = 0; i < 4; i++)
            cp_async16(&smem[OFF_WP + (wprow * WP_ROWSTRIDE + wpn + i) * 4], wp + i);
        CP_COMMIT();
    }
    float4 xv[2];
#pragma unroll
    for (int i = 0; i < 2; i++)
        xv[i] = xok ? *(const float4*)(xbase + i * 4) : make_float4(0.f, 0.f, 0.f, 0.f);

    for (int kt = 0; kt < 8; kt++) {
        int cur = kt & 1;
        // convert + store x tile (single buffer; prior compute fenced by loop-end barrier)
#pragma unroll
        for (int i = 0; i < 2; i++) {
            uint4 b = make_uint4(tf32_bits(xv[i].x), tf32_bits(xv[i].y),
                                 tf32_bits(xv[i].z), tf32_bits(xv[i].w));
            *(uint4*)&xs[xrow * XS_STRIDE + xkq + i * 4] = b;
        }
        CP_WAIT0();
        __syncthreads();

        if (kt < 7) {
            int nb = 1 - cur;
            const uint4* wp = &g_wp[(size_t)((kt + 1) * 16 + wprow) * OUT_DIM + n0 + wpn];
#pragma unroll
            for (int i = 0; i < 4; i++)
                cp_async16(&smem[OFF_WP + nb * WP_BUF + (wprow * WP_ROWSTRIDE + wpn + i) * 4], wp + i);
            CP_COMMIT();
            const float* xn = xbase + (kt + 1) * 32;
#pragma unroll
            for (int i = 0; i < 2; i++)
                xv[i] = xok ? *(const float4*)(xn + i * 4) : make_float4(0.f, 0.f, 0.f, 0.f);
        }

        const uint4* wpc = (const uint4*)&smem[OFF_WP + cur * WP_BUF];
#pragma unroll
        for (int kk = 0; kk < 32; kk += 8) {
            uint32_t a[2][4];
#pragma unroll
            for (int mt = 0; mt < 2; mt++) {
                int rbase = (wm + mt * 16 + g) * XS_STRIDE + kk;
                a[mt][0] = xs[rbase + t];
                a[mt][1] = xs[rbase + 8 * XS_STRIDE + t];
                a[mt][2] = xs[rbase + t + 4];
                a[mt][3] = xs[rbase + 8 * XS_STRIDE + t + 4];
            }
            uint4 bf[4];
#pragma unroll
            for (int nt = 0; nt < 4; nt++)
                bf[nt] = wpc[((kk >> 3) * 4 + t) * WP_ROWSTRIDE + wn + nt * 8 + g];
            // hi pass then lo pass: 16 independent accumulators, no back-to-back RAW
#pragma unroll
            for (int nt = 0; nt < 4; nt++) {
                mma_tf32(acc[0][nt], a[0][0], a[0][1], a[0][2], a[0][3], bf[nt].x, bf[nt].y);
                mma_tf32(acc[1][nt], a[1][0], a[1][1], a[1][2], a[1][3], bf[nt].x, bf[nt].y);
            }
#pragma unroll
            for (int nt = 0; nt < 4; nt++) {
                mma_tf32(acc[0][nt], a[0][0], a[0][1], a[0][2], a[0][3], bf[nt].z, bf[nt].w);
                mma_tf32(acc[1][nt], a[1][0], a[1][1], a[1][2], a[1][3], bf[nt].z, bf[nt].w);
            }
        }
        __syncthreads();
    }

    // epilogue: store h + fused attention-logit partials
    int head = (n0 + wn) >> 6;   // 32-col warp block never straddles a 64-wide head
#pragma unroll
    for (int mt = 0; mt < 2; mt++) {
        int r0 = m0 + wm + mt * 16 + g;
        int r1 = r0 + 8;
        float s0 = 0.f, d0 = 0.f, s1 = 0.f, d1 = 0.f;
#pragma unroll
        for (int nt = 0; nt < 4; nt++) {
            int c = n0 + wn + nt * 8 + 2 * t;
            if (r0 < N) *(float2*)&g_h[(size_t)r0 * OUT_DIM + c] =
                make_float2(acc[mt][nt][0], acc[mt][nt][1]);
            if (r1 < N) *(float2*)&g_h[(size_t)r1 * OUT_DIM + c] =
                make_float2(acc[mt][nt][2], acc[mt][nt][3]);
            float as0 = __ldg(&att_src[c]), as1 = __ldg(&att_src[c + 1]);
            float ad0 = __ldg(&att_dst[c]), ad1 = __ldg(&att_dst[c + 1]);
            s0 += acc[mt][nt][0] * as0 + acc[mt][nt][1] * as1;
            d0 += acc[mt][nt][0] * ad0 + acc[mt][nt][1] * ad1;
            s1 += acc[mt][nt][2] * as0 + acc[mt][nt][3] * as1;
            d1 += acc[mt][nt][2] * ad0 + acc[mt][nt][3] * ad1;
        }
#pragma unroll
        for (int off = 2; off >= 1; off >>= 1) {
            s0 += __shfl_down_sync(0xffffffffu, s0, off, 4);
            d0 += __shfl_down_sync(0xffffffffu, d0, off, 4);
            s1 += __shfl_down_sync(0xffffffffu, s1, off, 4);
            d1 += __shfl_down_sync(0xffffffffu, d1, off, 4);
        }
        if (t == 0) {
            if (r0 < N) {
                atomicAdd(&g_as[r0 * NHEAD + head], s0);
                atomicAdd(&g_ad[r0 * NHEAD + head], d0);
            }
            if (r1 < N) {
                atomicAdd(&g_as[r1 * NHEAD + head], s1);
                atomicAdd(&g_ad[r1 * NHEAD + head], d1);
            }
        }
    }
}

// ---------------- K3b: exclusive scan (single block) ----------------
__global__ __launch_bounds__(1024) void k_scan(int N) {
    __shared__ int wsum[32];
    int tid = threadIdx.x;
    int chunk = (N + 1023) >> 10;
    int base = tid * chunk;
    int local = 0;
    for (int i = 0; i < chunk; i++) {
        int idx = base + i;
        if (idx < N) local += g_cnt[idx];
    }
    int lane = tid & 31, w = tid >> 5;
    int v = local;
#pragma unroll
    for (int off = 1; off < 32; off <<= 1) {
        int t = __shfl_up_sync(0xffffffffu, v, off);
        if (lane >= off) v += t;
    }
    if (lane == 31) wsum[w] = v;
    __syncthreads();
    if (w == 0) {
        int sv = wsum[lane];
#pragma unroll
        for (int off = 1; off < 32; off <<= 1) {
            int t = __shfl_up_sync(0xffffffffu, sv, off);
            if (lane >= off) sv += t;
        }
        wsum[lane] = sv;
    }
    __syncthreads();
    int excl = v - local + (w > 0 ? wsum[w - 1] : 0);
    int run = excl;
    for (int i = 0; i < chunk; i++) {
        int idx = base + i;
        if (idx < N) {
            g_start[idx] = run;
            run += g_cnt[idx];
        }
    }
    if (tid == 1023) g_start[N] = run;
}

// ---------------- K3c: fill CSR ----------------
__global__ void k_fill(const int* __restrict__ ei, int E, int N) {
    int Etot = E + N;
    int stride = gridDim.x * blockDim.x;
    for (int i = blockIdx.x * blockDim.x + threadIdx.x; i < Etot; i += stride) {
        int src, dst;
        if (i < E) { src = ei[i]; dst = ei[E + i]; }
        else       { src = dst = i - E; }
        int pos = g_start[dst] + atomicAdd(&g_fill[dst], 1);
        g_csr[pos] = src;
    }
}

// ---------------- K4: per-node softmax over CSR segment (8 lanes per node) ----------------
__global__ void k_soft(int N) {
    int g = blockIdx.x * blockDim.x + threadIdx.x;
    int node = g >> 3;
    int sub = g & 7;
    bool valid = node < N;
    int nc = valid ? node : (N - 1);
    int start = g_start[nc], end = g_start[nc + 1];
    float4 ad = *(const float4*)&g_ad[nc * NHEAD];
    float4 m = make_float4(-3.4e38f, -3.4e38f, -3.4e38f, -3.4e38f);
    for (int p = start + sub; p < end; p += 8) {
        int src = g_csr[p];
        float4 as = *(const float4*)&g_as[src * NHEAD];
        m = max4(m, lrelu4(add4(as, ad)));
    }
#pragma unroll
    for (int off = 4; off >= 1; off >>= 1) {
        m.x = fmaxf(m.x, __shfl_xor_sync(0xffffffffu, m.x, off, 8));
        m.y = fmaxf(m.y, __shfl_xor_sync(0xffffffffu, m.y, off, 8));
        m.z = fmaxf(m.z, __shfl_xor_sync(0xffffffffu, m.z, off, 8));
        m.w = fmaxf(m.w, __shfl_xor_sync(0xffffffffu, m.w, off, 8));
    }
    float4 s = make_float4(0.f, 0.f, 0.f, 0.f);
    for (int p = start + sub; p < end; p += 8) {
        int src = g_csr[p];
        float4 as = *(const float4*)&g_as[src * NHEAD];
        float4 e = lrelu4(add4(as, ad));
        float4 wv = make_float4(__expf(e.x - m.x), __expf(e.y - m.y),
                                __expf(e.z - m.z), __expf(e.w - m.w));
        if (valid) *(float4*)&g_w[(size_t)p * NHEAD] = wv;
        s = add4(s, wv);
    }
#pragma unroll
    for (int off = 4; off >= 1; off >>= 1) {
        s.x += __shfl_xor_sync(0xffffffffu, s.x, off, 8);
        s.y += __shfl_xor_sync(0xffffffffu, s.y, off, 8);
        s.z += __shfl_xor_sync(0xffffffffu, s.z, off, 8);
        s.w += __shfl_xor_sync(0xffffffffu, s.w, off, 8);
    }
    if (valid && sub == 0) *(float4*)&g_s[nc * NHEAD] = s;
}

// ---------------- K5: aggregate (64 threads per node, register accum, single store) ----------------
__global__ __launch_bounds__(256) void k_agg(const float* __restrict__ bias,
                                             float* __restrict__ out, int N) {
    int node = blockIdx.x * 4 + (threadIdx.x >> 6);
    if (node >= N) return;
    int j = threadIdx.x & 63;
    int head = j >> 4;
    int start = g_start[node], end = g_start[node + 1];
    float inv_s = __frcp_rn(g_s[node * NHEAD + head]);
    float4 acc = make_float4(0.f, 0.f, 0.f, 0.f);
    for (int p = start; p < end; p++) {
        int src = __ldg(&g_csr[p]);
        float alpha = g_w[(size_t)p * NHEAD + head] * inv_s;
        float4 hv = *(const float4*)&g_h[(size_t)src * OUT_DIM + j * 4];
        acc.x += alpha * hv.x;
        acc.y += alpha * hv.y;
        acc.z += alpha * hv.z;
        acc.w += alpha * hv.w;
    }
    float4 bv = *(const float4*)&bias[j * 4];
    acc = add4(acc, bv);
    *(float4*)&out[(size_t)node * OUT_DIM + j * 4] = acc;
}

// ---------------- launch ----------------
extern "C" void kernel_launch(void* const* d_in, const int* in_sizes, int n_in,
                              void* d_out, int out_size) {
    const float* x       = (const float*)d_in[0];
    const int*   ei      = (const int*)d_in[1];
    const float* W       = (const float*)d_in[2];
    const float* att_src = (const float*)d_in[3];
    const float* att_dst = (const float*)d_in[4];
    const float* bias    = (const float*)d_in[5];
    float* out = (float*)d_out;

    int N = in_sizes[0] / IN_DIM;
    int E = in_sizes[1] / 2;
    int Etot = E + N;

    cudaFuncSetAttribute(k_gemm_mma, cudaFuncAttributeMaxDynamicSharedMemorySize, SM_GEMM_BYTES);

    k_zero<<<(4 * N + 255) / 256, 256>>>(N);
    k_wt<<<((IN_DIM / 2) * OUT_DIM + 255) / 256, 256>>>(W);
    k_hist<<<(Etot + 255) / 256, 256>>>(ei, E, N);
    dim3 ggrid((N + 127) / 128, OUT_DIM / 128);
    k_gemm_mma<<<ggrid, 512, SM_GEMM_BYTES>>>(x, att_src, att_dst, N);  // launch #4 for ncu
    k_scan<<<1, 1024>>>(N);
    k_fill<<<(Etot + 255) / 256, 256>>>(ei, E, N);
    k_soft<<<(N * 8 + 255) / 256, 256>>>(N);
    k_agg<<<(N + 3) / 4, 256>>>(bias, out, N);
}

// round 9
// speedup vs baseline: 1.0149x; 1.0149x over previous
#include <cuda_runtime.h>
#include <math.h>
#include <stdint.h>

#define IN_DIM  256
#define OUT_DIM 256   // H*D = 4*64
#define NHEAD   4
#define NMAX    50000
#define EMAX    800000
#define ETOTMAX (EMAX + NMAX)

// ---------------- scratch (__device__ globals; allocation-free) ----------------
__device__ float    g_h[(size_t)NMAX * OUT_DIM];     // 51.2 MB transformed features
__device__ float    g_as[NMAX * NHEAD];
__device__ float    g_ad[NMAX * NHEAD];
__device__ int      g_cnt[NMAX];
__device__ int      g_fill[NMAX];
__device__ int      g_start[NMAX + 1];
__device__ int      g_csr[ETOTMAX];
__device__ float    g_w[(size_t)ETOTMAX * NHEAD];
__device__ float    g_s[NMAX * NHEAD];
// W fragment-packed: pr = (k>>3)*4 + (k&3), element = {hi[k], hi[k+4], lo[k], lo[k+4]} at col n
__device__ uint4    g_wp[(IN_DIM / 2) * OUT_DIM];

__device__ __forceinline__ unsigned tf32_bits(float f) {
    unsigned r; asm("cvt.rna.tf32.f32 %0, %1;" : "=r"(r) : "f"(f)); return r;
}

__device__ __forceinline__ void mma_tf32(float* c, uint32_t a0, uint32_t a1,
                                         uint32_t a2, uint32_t a3,
                                         uint32_t b0, uint32_t b1) {
    asm("mma.sync.aligned.m16n8k8.row.col.f32.tf32.tf32.f32 "
        "{%0,%1,%2,%3},{%4,%5,%6,%7},{%8,%9},{%0,%1,%2,%3};"
        : "+f"(c[0]), "+f"(c[1]), "+f"(c[2]), "+f"(c[3])
        : "r"(a0), "r"(a1), "r"(a2), "r"(a3), "r"(b0), "r"(b1));
}

__device__ __forceinline__ void cp_async16(unsigned* smem_ptr, const void* gptr) {
    uint32_t s = (uint32_t)__cvta_generic_to_shared(smem_ptr);
    asm volatile("cp.async.cg.shared.global [%0], [%1], 16;" :: "r"(s), "l"(gptr) : "memory");
}
#define CP_COMMIT() asm volatile("cp.async.commit_group;" ::: "memory")
#define CP_WAIT0()  asm volatile("cp.async.wait_group 0;" ::: "memory")

__device__ __forceinline__ float lrelu(float x) { return x > 0.f ? x : 0.2f * x; }
__device__ __forceinline__ float4 lrelu4(float4 a) {
    return make_float4(lrelu(a.x), lrelu(a.y), lrelu(a.z), lrelu(a.w));
}
__device__ __forceinline__ float4 add4(float4 a, float4 b) {
    return make_float4(a.x + b.x, a.y + b.y, a.z + b.z, a.w + b.w);
}
__device__ __forceinline__ float4 max4(float4 a, float4 b) {
    return make_float4(fmaxf(a.x, b.x), fmaxf(a.y, b.y), fmaxf(a.z, b.z), fmaxf(a.w, b.w));
}

// ---------------- K0: zero counters + logits accumulators ----------------
__global__ void k_zero(int N) {
    int stride = gridDim.x * blockDim.x;
    int gid = blockIdx.x * blockDim.x + threadIdx.x;
    for (int i = gid; i < 2 * N; i += stride) {
        if (i < N) g_cnt[i] = 0; else g_fill[i - N] = 0;
    }
    for (int i = gid; i < 4 * N; i += stride) { g_as[i] = 0.f; g_ad[i] = 0.f; }
}

// ---------------- K0b: W -> fragment-packed tf32 hi/lo ----------------
__global__ void k_wt(const float* __restrict__ W) {
    int idx = blockIdx.x * blockDim.x + threadIdx.x;     // (pr, n)
    if (idx >= (IN_DIM / 2) * OUT_DIM) return;
    int pr = idx >> 8, n = idx & 255;
    int q = pr >> 2, t = pr & 3;
    int k = q * 8 + t;
    float w0 = W[(size_t)k * OUT_DIM + n];
    float w1 = W[(size_t)(k + 4) * OUT_DIM + n];
    unsigned h0 = tf32_bits(w0), h1 = tf32_bits(w1);
    unsigned l0 = tf32_bits(w0 - __uint_as_float(h0));
    unsigned l1 = tf32_bits(w1 - __uint_as_float(h1));
    g_wp[idx] = make_uint4(h0, h1, l0, l1);
}

// ---------------- K3a: histogram of dst ----------------
__global__ void k_hist(const int* __restrict__ ei, int E, int N) {
    int Etot = E + N;
    int stride = gridDim.x * blockDim.x;
    for (int i = blockIdx.x * blockDim.x + threadIdx.x; i < Etot; i += stride) {
        int dst = (i < E) ? ei[E + i] : (i - E);
        atomicAdd(&g_cnt[dst], 1);
    }
}

// ---------------- K1: GEMM h = x @ W (mma.sync tf32 2-pass) + fused att logits ----------------
// BM=128, BN=128, BK=32; 16 warps, warp tile 32x32; 2 CTAs/SM.
// FULL double buffering (x and W), ONE barrier per K-tile.
#define XS_STRIDE 36
#define XS_BUF (128 * XS_STRIDE)          // 4608 words per buffer
#define WP_ROWSTRIDE 130                  // uint4 units; conflict-free (see R8 analysis)
#define WP_BUF (16 * WP_ROWSTRIDE * 4)    // 8320 words per buffer
#define OFF_XS 0
#define OFF_WP (2 * XS_BUF)                   // 9216
#define SM_GEMM_WORDS (OFF_WP + 2 * WP_BUF)   // 25856 words
#define SM_GEMM_BYTES (SM_GEMM_WORDS * 4)     // 103424 B
__global__ __launch_bounds__(512, 2) void k_gemm_mma(const float* __restrict__ x,
                                                     const float* __restrict__ att_src,
                                                     const float* __restrict__ att_dst, int N) {
    extern __shared__ unsigned smem[];
    int tid = threadIdx.x;
    int wid = tid >> 5, lane = tid & 31;
    int g = lane >> 2, t = lane & 3;
    int m0 = blockIdx.x * 128;
    int n0 = blockIdx.y * 128;
    int wm = (wid & 3) * 32;        // warp row offset
    int wn = (wid >> 2) * 32;       // warp col offset

    float acc[2][4][4];
#pragma unroll
    for (int mt = 0; mt < 2; mt++)
#pragma unroll
        for (int nt = 0; nt < 4; nt++)
#pragma unroll
            for (int i = 0; i < 4; i++) acc[mt][nt][i] = 0.f;

    int xrow = tid >> 2;                 // 0..127
    int xkq  = (tid & 3) * 8;            // 0,8,16,24
    int wprow = tid >> 5;                // 0..15
    int wpn   = lane * 4;                // 0..124
    int grow = m0 + xrow;
    bool xok = grow < N;
    const float* xbase = &x[(size_t)grow * IN_DIM + xkq];

    // prologue: W[0] via cp.async; x[0] via LDG -> cvt -> STS into buffer 0
    {
        const uint4* wp = &g_wp[(size_t)wprow * OUT_DIM + n0 + wpn];
#pragma unroll
        for (int i = 0; i < 4; i++)
            cp_async16(&smem[OFF_WP + (wprow * WP_ROWSTRIDE + wpn + i) * 4], wp + i);
        CP_COMMIT();
        float4 x0[2];
#pragma unroll
        for (int i = 0; i < 2; i++)
            x0[i] = xok ? *(const float4*)(xbase + i * 4) : make_float4(0.f, 0.f, 0.f, 0.f);
#pragma unroll
        for (int i = 0; i < 2; i++) {
            uint4 b = make_uint4(tf32_bits(x0[i].x), tf32_bits(x0[i].y),
                                 tf32_bits(x0[i].z), tf32_bits(x0[i].w));
            *(uint4*)&smem[OFF_XS + xrow * XS_STRIDE + xkq + i * 4] = b;
        }
        CP_WAIT0();
    }
    __syncthreads();

    for (int kt = 0; kt < 8; kt++) {
        int cur = kt & 1;
        int nb = 1 - cur;
        float4 xv[2];
        if (kt < 7) {
            // issue next W + next x loads; latency hidden under compute below
            const uint4* wp = &g_wp[(size_t)((kt + 1) * 16 + wprow) * OUT_DIM + n0 + wpn];
#pragma unroll
            for (int i = 0; i < 4; i++)
                cp_async16(&smem[OFF_WP + nb * WP_BUF + (wprow * WP_ROWSTRIDE + wpn + i) * 4], wp + i);
            CP_COMMIT();
            const float* xn = xbase + (kt + 1) * 32;
#pragma unroll
            for (int i = 0; i < 2; i++)
                xv[i] = xok ? *(const float4*)(xn + i * 4) : make_float4(0.f, 0.f, 0.f, 0.f);
        }

        const unsigned* xs = smem + OFF_XS + cur * XS_BUF;
        const uint4* wpc = (const uint4*)&smem[OFF_WP + cur * WP_BUF];
#pragma unroll
        for (int kk = 0; kk < 32; kk += 8) {
            uint32_t a[2][4];
#pragma unroll
            for (int mt = 0; mt < 2; mt++) {
                int rbase = (wm + mt * 16 + g) * XS_STRIDE + kk;
                a[mt][0] = xs[rbase + t];
                a[mt][1] = xs[rbase + 8 * XS_STRIDE + t];
                a[mt][2] = xs[rbase + t + 4];
                a[mt][3] = xs[rbase + 8 * XS_STRIDE + t + 4];
            }
            uint4 bf[4];
#pragma unroll
            for (int nt = 0; nt < 4; nt++)
                bf[nt] = wpc[((kk >> 3) * 4 + t) * WP_ROWSTRIDE + wn + nt * 8 + g];
            // hi pass then lo pass: 16 independent accumulators
#pragma unroll
            for (int nt = 0; nt < 4; nt++) {
                mma_tf32(acc[0][nt], a[0][0], a[0][1], a[0][2], a[0][3], bf[nt].x, bf[nt].y);
                mma_tf32(acc[1][nt], a[1][0], a[1][1], a[1][2], a[1][3], bf[nt].x, bf[nt].y);
            }
#pragma unroll
            for (int nt = 0; nt < 4; nt++) {
                mma_tf32(acc[0][nt], a[0][0], a[0][1], a[0][2], a[0][3], bf[nt].z, bf[nt].w);
                mma_tf32(acc[1][nt], a[1][0], a[1][1], a[1][2], a[1][3], bf[nt].z, bf[nt].w);
            }
        }

        if (kt < 7) {
            // store next x tile into the other buffer (no reader until barrier)
            unsigned* xsn = smem + OFF_XS + nb * XS_BUF;
#pragma unroll
            for (int i = 0; i < 2; i++) {
                uint4 b = make_uint4(tf32_bits(xv[i].x), tf32_bits(xv[i].y),
                                     tf32_bits(xv[i].z), tf32_bits(xv[i].w));
                *(uint4*)&xsn[xrow * XS_STRIDE + xkq + i * 4] = b;
            }
            CP_WAIT0();
        }
        __syncthreads();   // single barrier per K-tile
    }

    // epilogue: store h + fused attention-logit partials
    int head = (n0 + wn) >> 6;
#pragma unroll
    for (int mt = 0; mt < 2; mt++) {
        int r0 = m0 + wm + mt * 16 + g;
        int r1 = r0 + 8;
        float s0 = 0.f, d0 = 0.f, s1 = 0.f, d1 = 0.f;
#pragma unroll
        for (int nt = 0; nt < 4; nt++) {
            int c = n0 + wn + nt * 8 + 2 * t;
            if (r0 < N) *(float2*)&g_h[(size_t)r0 * OUT_DIM + c] =
                make_float2(acc[mt][nt][0], acc[mt][nt][1]);
            if (r1 < N) *(float2*)&g_h[(size_t)r1 * OUT_DIM + c] =
                make_float2(acc[mt][nt][2], acc[mt][nt][3]);
            float as0 = __ldg(&att_src[c]), as1 = __ldg(&att_src[c + 1]);
            float ad0 = __ldg(&att_dst[c]), ad1 = __ldg(&att_dst[c + 1]);
            s0 += acc[mt][nt][0] * as0 + acc[mt][nt][1] * as1;
            d0 += acc[mt][nt][0] * ad0 + acc[mt][nt][1] * ad1;
            s1 += acc[mt][nt][2] * as0 + acc[mt][nt][3] * as1;
            d1 += acc[mt][nt][2] * ad0 + acc[mt][nt][3] * ad1;
        }
#pragma unroll
        for (int off = 2; off >= 1; off >>= 1) {
            s0 += __shfl_down_sync(0xffffffffu, s0, off, 4);
            d0 += __shfl_down_sync(0xffffffffu, d0, off, 4);
            s1 += __shfl_down_sync(0xffffffffu, s1, off, 4);
            d1 += __shfl_down_sync(0xffffffffu, d1, off, 4);
        }
        if (t == 0) {
            if (r0 < N) {
                atomicAdd(&g_as[r0 * NHEAD + head], s0);
                atomicAdd(&g_ad[r0 * NHEAD + head], d0);
            }
            if (r1 < N) {
                atomicAdd(&g_as[r1 * NHEAD + head], s1);
                atomicAdd(&g_ad[r1 * NHEAD + head], d1);
            }
        }
    }
}

// ---------------- K3b: exclusive scan (single block) ----------------
__global__ __launch_bounds__(1024) void k_scan(int N) {
    __shared__ int wsum[32];
    int tid = threadIdx.x;
    int chunk = (N + 1023) >> 10;
    int base = tid * chunk;
    int local = 0;
    for (int i = 0; i < chunk; i++) {
        int idx = base + i;
        if (idx < N) local += g_cnt[idx];
    }
    int lane = tid & 31, w = tid >> 5;
    int v = local;
#pragma unroll
    for (int off = 1; off < 32; off <<= 1) {
        int t = __shfl_up_sync(0xffffffffu, v, off);
        if (lane >= off) v += t;
    }
    if (lane == 31) wsum[w] = v;
    __syncthreads();
    if (w == 0) {
        int sv = wsum[lane];
#pragma unroll
        for (int off = 1; off < 32; off <<= 1) {
            int t = __shfl_up_sync(0xffffffffu, sv, off);
            if (lane >= off) sv += t;
        }
        wsum[lane] = sv;
    }
    __syncthreads();
    int excl = v - local + (w > 0 ? wsum[w - 1] : 0);
    int run = excl;
    for (int i = 0; i < chunk; i++) {
        int idx = base + i;
        if (idx < N) {
            g_start[idx] = run;
            run += g_cnt[idx];
        }
    }
    if (tid == 1023) g_start[N] = run;
}

// ---------------- K3c: fill CSR ----------------
__global__ void k_fill(const int* __restrict__ ei, int E, int N) {
    int Etot = E + N;
    int stride = gridDim.x * blockDim.x;
    for (int i = blockIdx.x * blockDim.x + threadIdx.x; i < Etot; i += stride) {
        int src, dst;
        if (i < E) { src = ei[i]; dst = ei[E + i]; }
        else       { src = dst = i - E; }
        int pos = g_start[dst] + atomicAdd(&g_fill[dst], 1);
        g_csr[pos] = src;
    }
}

// ---------------- K4: per-node softmax over CSR segment (8 lanes per node) ----------------
__global__ void k_soft(int N) {
    int g = blockIdx.x * blockDim.x + threadIdx.x;
    int node = g >> 3;
    int sub = g & 7;
    bool valid = node < N;
    int nc = valid ? node : (N - 1);
    int start = g_start[nc], end = g_start[nc + 1];
    float4 ad = *(const float4*)&g_ad[nc * NHEAD];
    float4 m = make_float4(-3.4e38f, -3.4e38f, -3.4e38f, -3.4e38f);
    for (int p = start + sub; p < end; p += 8) {
        int src = g_csr[p];
        float4 as = *(const float4*)&g_as[src * NHEAD];
        m = max4(m, lrelu4(add4(as, ad)));
    }
#pragma unroll
    for (int off = 4; off >= 1; off >>= 1) {
        m.x = fmaxf(m.x, __shfl_xor_sync(0xffffffffu, m.x, off, 8));
        m.y = fmaxf(m.y, __shfl_xor_sync(0xffffffffu, m.y, off, 8));
        m.z = fmaxf(m.z, __shfl_xor_sync(0xffffffffu, m.z, off, 8));
        m.w = fmaxf(m.w, __shfl_xor_sync(0xffffffffu, m.w, off, 8));
    }
    float4 s = make_float4(0.f, 0.f, 0.f, 0.f);
    for (int p = start + sub; p < end; p += 8) {
        int src = g_csr[p];
        float4 as = *(const float4*)&g_as[src * NHEAD];
        float4 e = lrelu4(add4(as, ad));
        float4 wv = make_float4(__expf(e.x - m.x), __expf(e.y - m.y),
                                __expf(e.z - m.z), __expf(e.w - m.w));
        if (valid) *(float4*)&g_w[(size_t)p * NHEAD] = wv;
        s = add4(s, wv);
    }
#pragma unroll
    for (int off = 4; off >= 1; off >>= 1) {
        s.x += __shfl_xor_sync(0xffffffffu, s.x, off, 8);
        s.y += __shfl_xor_sync(0xffffffffu, s.y, off, 8);
        s.z += __shfl_xor_sync(0xffffffffu, s.z, off, 8);
        s.w += __shfl_xor_sync(0xffffffffu, s.w, off, 8);
    }
    if (valid && sub == 0) *(float4*)&g_s[nc * NHEAD] = s;
}

// ---------------- K5: aggregate (64 threads per node, register accum, single store) ----------------
__global__ __launch_bounds__(256) void k_agg(const float* __restrict__ bias,
                                             float* __restrict__ out, int N) {
    int node = blockIdx.x * 4 + (threadIdx.x >> 6);
    if (node >= N) return;
    int j = threadIdx.x & 63;
    int head = j >> 4;
    int start = g_start[node], end = g_start[node + 1];
    float inv_s = __frcp_rn(g_s[node * NHEAD + head]);
    float4 acc = make_float4(0.f, 0.f, 0.f, 0.f);
    for (int p = start; p < end; p++) {
        int src = __ldg(&g_csr[p]);
        float alpha = g_w[(size_t)p * NHEAD + head] * inv_s;
        float4 hv = *(const float4*)&g_h[(size_t)src * OUT_DIM + j * 4];
        acc.x += alpha * hv.x;
        acc.y += alpha * hv.y;
        acc.z += alpha * hv.z;
        acc.w += alpha * hv.w;
    }
    float4 bv = *(const float4*)&bias[j * 4];
    acc = add4(acc, bv);
    *(float4*)&out[(size_t)node * OUT_DIM + j * 4] = acc;
}

// ---------------- launch ----------------
extern "C" void kernel_launch(void* const* d_in, const int* in_sizes, int n_in,
                              void* d_out, int out_size) {
    const float* x       = (const float*)d_in[0];
    const int*   ei      = (const int*)d_in[1];
    const float* W       = (const float*)d_in[2];
    const float* att_src = (const float*)d_in[3];
    const float* att_dst = (const float*)d_in[4];
    const float* bias    = (const float*)d_in[5];
    float* out = (float*)d_out;

    int N = in_sizes[0] / IN_DIM;
    int E = in_sizes[1] / 2;
    int Etot = E + N;

    cudaFuncSetAttribute(k_gemm_mma, cudaFuncAttributeMaxDynamicSharedMemorySize, SM_GEMM_BYTES);

    k_zero<<<(4 * N + 255) / 256, 256>>>(N);
    k_wt<<<((IN_DIM / 2) * OUT_DIM + 255) / 256, 256>>>(W);
    k_hist<<<(Etot + 255) / 256, 256>>>(ei, E, N);
    dim3 ggrid((N + 127) / 128, OUT_DIM / 128);
    k_gemm_mma<<<ggrid, 512, SM_GEMM_BYTES>>>(x, att_src, att_dst, N);  // launch #4 for ncu
    k_scan<<<1, 1024>>>(N);
    k_fill<<<(Etot + 255) / 256, 256>>>(ei, E, N);
    k_soft<<<(N * 8 + 255) / 256, 256>>>(N);
    k_agg<<<(N + 3) / 4, 256>>>(bias, out, N);
}